// round 1
// baseline (speedup 1.0000x reference)
#include <cuda_runtime.h>
#include <cuda_bf16.h>
#include <math.h>

// ---------------------------------------------------------------------------
// FNet block:
//   ft = Re( FFT_seq( D * x reversed along hidden ) )      [math identity]
//   t  = LayerNorm(x + ft) * g + b
//   h  = GELU(t @ w1 + b1)
//   out= (h @ w2 + b2) * mask
// Shapes: x [8, 2048, 1024] fp32. B=8, S=2048, D=1024.
// ---------------------------------------------------------------------------

#define B_ 8
#define S_ 2048
#define D_ 1024
#define ROWS (B_ * S_)          // 16384
#define ELEMS ((long)ROWS * D_) // 16,777,216

// Scratch (static device globals — no allocation allowed)
__device__ float g_ft[ELEMS];
__device__ float g_t[ELEMS];
__device__ float g_h[ELEMS];

// ---------------------------------------------------------------------------
// Kernel 1: per-(b, column) 2048-point complex FFT along seq, real input.
// CTA handles source column c; writes D * Re(FFT) into output column
// dout = (D - c) & (D - 1)   (the F_D^2 index reversal).
// ---------------------------------------------------------------------------
__global__ __launch_bounds__(256) void fft_seq_kernel(
    const float* __restrict__ x, float* __restrict__ ft)
{
    __shared__ float2 sa[S_];   // 16 KB
    const int c   = blockIdx.x;   // source hidden column
    const int b   = blockIdx.y;
    const int tid = threadIdx.x;

    const float* xp = x + (long)b * S_ * D_ + c;

    // Load in bit-reversed order (DIT -> natural-order output)
    #pragma unroll
    for (int i = tid; i < S_; i += 256) {
        int r = __brev(i) >> 21;            // 11-bit reversal
        sa[i] = make_float2(xp[(long)r * D_], 0.0f);
    }
    __syncthreads();

    int half = 1;
    #pragma unroll
    for (int stage = 0; stage < 11; stage++) {
        for (int k = tid; k < S_ / 2; k += 256) {
            int j    = k & (half - 1);
            int base = (k - j) << 1;
            int p    = base + j;
            float sn, cs;
            sincospif(-(float)j / (float)half, &sn, &cs);  // angle = -pi*j/half
            float2 u = sa[p];
            float2 v = sa[p + half];
            float2 t = make_float2(cs * v.x - sn * v.y,
                                   cs * v.y + sn * v.x);
            sa[p]        = make_float2(u.x + t.x, u.y + t.y);
            sa[p + half] = make_float2(u.x - t.x, u.y - t.y);
        }
        half <<= 1;
        __syncthreads();
    }

    const int dout = (D_ - c) & (D_ - 1);
    float* fp = ft + (long)b * S_ * D_ + dout;
    for (int s = tid; s < S_; s += 256) {
        fp[(long)s * D_] = (float)D_ * sa[s].x;
    }
}

// ---------------------------------------------------------------------------
// Kernel 2: t = LayerNorm(x + ft) * gamma + beta   (one CTA per row of 1024)
// ---------------------------------------------------------------------------
__device__ __forceinline__ float block_sum_256(float val, float* sh) {
    #pragma unroll
    for (int o = 16; o > 0; o >>= 1)
        val += __shfl_xor_sync(0xFFFFFFFFu, val, o);
    int lane = threadIdx.x & 31;
    int w    = threadIdx.x >> 5;
    if (lane == 0) sh[w] = val;
    __syncthreads();
    if (w == 0) {
        float v = (lane < 8) ? sh[lane] : 0.0f;
        #pragma unroll
        for (int o = 4; o > 0; o >>= 1)
            v += __shfl_xor_sync(0xFFFFFFFFu, v, o);
        if (lane == 0) sh[0] = v;
    }
    __syncthreads();
    float r = sh[0];
    __syncthreads();   // safe reuse of sh
    return r;
}

__global__ __launch_bounds__(256) void add_ln_kernel(
    const float* __restrict__ x, const float* __restrict__ ft,
    const float* __restrict__ gamma, const float* __restrict__ beta,
    float* __restrict__ out)
{
    __shared__ float sh[8];
    const int row  = blockIdx.x;
    const int tid  = threadIdx.x;
    const long base = (long)row * D_;

    float v[4];
    float s = 0.0f;
    #pragma unroll
    for (int i = 0; i < 4; i++) {
        int idx = tid + i * 256;
        v[i] = x[base + idx] + ft[base + idx];
        s += v[i];
    }
    float mu = block_sum_256(s, sh) * (1.0f / D_);

    float sq = 0.0f;
    #pragma unroll
    for (int i = 0; i < 4; i++) {
        float d = v[i] - mu;
        sq += d * d;
    }
    float var = block_sum_256(sq, sh) * (1.0f / D_);
    float rs  = rsqrtf(var + 1e-5f);

    #pragma unroll
    for (int i = 0; i < 4; i++) {
        int idx = tid + i * 256;
        out[base + idx] = (v[i] - mu) * rs * gamma[idx] + beta[idx];
    }
}

// ---------------------------------------------------------------------------
// Kernel 3/4: tiled fp32 GEMM  C = A[M,K] @ B[K,N] + bias, fused epilogue.
// fuse == 0 : GELU(exact)         fuse == 1 : multiply by mask[row]
// BM=BN=128, BK=8, 256 threads, 8x8 per thread.
// ---------------------------------------------------------------------------
#define BM 128
#define BN 128
#define BK 8

__global__ __launch_bounds__(256) void gemm_fused_kernel(
    const float* __restrict__ A, const float* __restrict__ Bm,
    const float* __restrict__ bias, const float* __restrict__ mask,
    float* __restrict__ C, int M, int N, int K, int fuse)
{
    __shared__ float As[BK][BM];
    __shared__ float Bs[BK][BN];

    const int tid = threadIdx.x;
    const int bm  = blockIdx.y * BM;
    const int bn  = blockIdx.x * BN;
    const int ty  = tid >> 4;        // 0..15
    const int tx  = tid & 15;        // 0..15

    // A-tile load mapping: 2 threads per row, float4 each
    const int aRow = tid >> 1;               // 0..127
    const int aCol = (tid & 1) << 2;         // 0 or 4
    // B-tile load mapping: 32 threads per row, float4 each
    const int bRow = tid >> 5;               // 0..7
    const int bCol = (tid & 31) << 2;        // 0..124

    const float* Aptr = A + (long)(bm + aRow) * K + aCol;
    const float* Bptr = Bm + (long)bRow * N + bn + bCol;

    float acc[8][8];
    #pragma unroll
    for (int i = 0; i < 8; i++)
        #pragma unroll
        for (int j = 0; j < 8; j++)
            acc[i][j] = 0.0f;

    for (int k0 = 0; k0 < K; k0 += BK) {
        float4 av = *(const float4*)(Aptr + k0);
        float4 bv = *(const float4*)(Bptr + (long)k0 * N);
        As[aCol + 0][aRow] = av.x;
        As[aCol + 1][aRow] = av.y;
        As[aCol + 2][aRow] = av.z;
        As[aCol + 3][aRow] = av.w;
        *(float4*)&Bs[bRow][bCol] = bv;
        __syncthreads();

        #pragma unroll
        for (int k = 0; k < BK; k++) {
            float a[8], b[8];
            *(float4*)(a)     = *(const float4*)&As[k][ty * 8];
            *(float4*)(a + 4) = *(const float4*)&As[k][ty * 8 + 4];
            *(float4*)(b)     = *(const float4*)&Bs[k][tx * 8];
            *(float4*)(b + 4) = *(const float4*)&Bs[k][tx * 8 + 4];
            #pragma unroll
            for (int i = 0; i < 8; i++)
                #pragma unroll
                for (int j = 0; j < 8; j++)
                    acc[i][j] += a[i] * b[j];
        }
        __syncthreads();
    }

    #pragma unroll
    for (int i = 0; i < 8; i++) {
        int r = bm + ty * 8 + i;
        float mk = (fuse == 1) ? mask[r] : 0.0f;
        #pragma unroll
        for (int j = 0; j < 8; j++) {
            int cidx = bn + tx * 8 + j;
            float v = acc[i][j] + bias[cidx];
            if (fuse == 0) {
                v = 0.5f * v * (1.0f + erff(v * 0.70710678118654752f));
            } else {
                v *= mk;
            }
            C[(long)r * N + cidx] = v;
        }
    }
}

// ---------------------------------------------------------------------------
// Launch
// ---------------------------------------------------------------------------
extern "C" void kernel_launch(void* const* d_in, const int* in_sizes, int n_in,
                              void* d_out, int out_size)
{
    const float* x    = (const float*)d_in[0];
    const float* mask = (const float*)d_in[1];
    const float* ln_g = (const float*)d_in[2];
    const float* ln_b = (const float*)d_in[3];
    const float* w1   = (const float*)d_in[4];
    const float* b1   = (const float*)d_in[5];
    const float* w2   = (const float*)d_in[6];
    const float* b2   = (const float*)d_in[7];
    float* out = (float*)d_out;

    float *ft, *t, *h;
    cudaGetSymbolAddress((void**)&ft, g_ft);
    cudaGetSymbolAddress((void**)&t,  g_t);
    cudaGetSymbolAddress((void**)&h,  g_h);

    fft_seq_kernel<<<dim3(D_, B_), 256>>>(x, ft);
    add_ln_kernel<<<ROWS, 256>>>(x, ft, ln_g, ln_b, t);
    gemm_fused_kernel<<<dim3(D_ / BN, ROWS / BM), 256>>>(
        t, w1, b1, nullptr, h, ROWS, D_, D_, 0);
    gemm_fused_kernel<<<dim3(D_ / BN, ROWS / BM), 256>>>(
        h, w2, b2, mask, out, ROWS, D_, D_, 1);
}

// round 4
// speedup vs baseline: 2.1557x; 2.1557x over previous
#include <cuda_runtime.h>
#include <cuda_bf16.h>
#include <math.h>
#include <stdint.h>

// ===========================================================================
// FNet block on GB300 (compute_103 PTX path -> no tcgen05; use mma.sync HMMA)
//   ft  = Re(FFT_seq(D * reverse_hidden(x)))    [FFT_D^2 = D * index reversal]
//   t   = LayerNorm(x + ft)*g + b   -> bf16 (hi,lo) split
//   h   = GELU(t @ w1 + b1)         -> bf16x3 mma.sync GEMM, split epilogue
//   out = (h @ w2 + b2) * mask      -> bf16x3 mma.sync GEMM, fp32 epilogue
// ===========================================================================

#define B_ 8
#define S_ 2048
#define D_ 1024
#define ROWS (B_ * S_)
#define ELEMS ((long)ROWS * D_)

// ------------------------- device scratch (no allocs) ----------------------
__device__ __align__(256) float          g_ft[ELEMS];
__device__ __align__(256) __nv_bfloat16  g_thi[ELEMS];
__device__ __align__(256) __nv_bfloat16  g_tlo[ELEMS];
__device__ __align__(256) __nv_bfloat16  g_hhi[ELEMS];
__device__ __align__(256) __nv_bfloat16  g_hlo[ELEMS];
__device__ __align__(256) __nv_bfloat16  g_w1hi[D_ * D_];
__device__ __align__(256) __nv_bfloat16  g_w1lo[D_ * D_];
__device__ __align__(256) __nv_bfloat16  g_w2hi[D_ * D_];
__device__ __align__(256) __nv_bfloat16  g_w2lo[D_ * D_];
__device__ __align__(256) float2         g_tw[1024];

// ------------------------- helpers ----------------------------------------
__device__ __forceinline__ uint32_t smem_u32(const void* p) {
    uint32_t a;
    asm("{ .reg .u64 t; cvta.to.shared.u64 t, %1; cvt.u32.u64 %0, t; }"
        : "=r"(a) : "l"(p));
    return a;
}
__device__ __forceinline__ void cp16(uint32_t s, const void* g) {
    asm volatile("cp.async.cg.shared.global [%0], [%1], 16;" :: "r"(s), "l"(g));
}
#define CP_COMMIT() asm volatile("cp.async.commit_group;" ::: "memory")
#define CP_WAIT(n)  asm volatile("cp.async.wait_group %0;" :: "n"(n) : "memory")

__device__ __forceinline__ void ldsm_x4(uint32_t* r, uint32_t addr) {
    asm volatile("ldmatrix.sync.aligned.m8n8.x4.shared.b16 {%0,%1,%2,%3}, [%4];"
                 : "=r"(r[0]), "=r"(r[1]), "=r"(r[2]), "=r"(r[3]) : "r"(addr));
}
__device__ __forceinline__ void mma_bf16(float* c, const uint32_t* a, const uint32_t* b) {
    asm volatile("mma.sync.aligned.m16n8k16.row.col.f32.bf16.bf16.f32 "
                 "{%0,%1,%2,%3}, {%4,%5,%6,%7}, {%8,%9}, {%0,%1,%2,%3};"
                 : "+f"(c[0]), "+f"(c[1]), "+f"(c[2]), "+f"(c[3])
                 : "r"(a[0]), "r"(a[1]), "r"(a[2]), "r"(a[3]),
                   "r"(b[0]), "r"(b[1]));
}

// ===========================================================================
// Kernel 0a: twiddle table  tw[t] = exp(-i*pi*t/1024)
// ===========================================================================
__global__ void twinit_kernel(float2* __restrict__ tw) {
    int t = blockIdx.x * 256 + threadIdx.x;
    float s, c;
    sincospif(-(float)t / 1024.0f, &s, &c);
    tw[t] = make_float2(c, s);
}

// ===========================================================================
// Kernel 0b: weight transpose + bf16 hi/lo split.  w[K][N] -> wt_{hi,lo}[N][K]
// ===========================================================================
__global__ __launch_bounds__(256) void wsplit_kernel(
    const float* __restrict__ w, __nv_bfloat16* __restrict__ whi,
    __nv_bfloat16* __restrict__ wlo)
{
    __shared__ float tile[32][33];
    const int bx = blockIdx.x * 32;   // n block
    const int by = blockIdx.y * 32;   // k block
    const int tx = threadIdx.x, ty = threadIdx.y;
    for (int i = ty; i < 32; i += 8)
        tile[i][tx] = w[(long)(by + i) * D_ + bx + tx];
    __syncthreads();
    for (int i = ty; i < 32; i += 8) {
        int n = bx + i;
        int k = by + tx;
        float v = tile[tx][i];
        __nv_bfloat16 hi = __float2bfloat16(v);
        whi[(long)n * D_ + k] = hi;
        wlo[(long)n * D_ + k] = __float2bfloat16(v - __bfloat162float(hi));
    }
}

// ===========================================================================
// Kernel 1: FFT along seq, 8 adjacent hidden columns per CTA
// ===========================================================================
__global__ __launch_bounds__(512) void fft8_kernel(
    const float* __restrict__ x, float* __restrict__ ft,
    const float2* __restrict__ tw)
{
    extern __shared__ float2 sa[];   // [2048][8] = 128KB
    const int c0  = blockIdx.x * 8;
    const int b   = blockIdx.y;
    const int tid = threadIdx.x;

    const float* xp = x + (long)b * S_ * D_ + c0;
    for (int r = tid; r < S_; r += 512) {
        int br = __brev(r) >> 21;
        float4 v0 = *(const float4*)(xp + (long)r * D_);
        float4 v1 = *(const float4*)(xp + (long)r * D_ + 4);
        float2* d = sa + br * 8;
        d[0] = make_float2(v0.x, 0.f); d[1] = make_float2(v0.y, 0.f);
        d[2] = make_float2(v0.z, 0.f); d[3] = make_float2(v0.w, 0.f);
        d[4] = make_float2(v1.x, 0.f); d[5] = make_float2(v1.y, 0.f);
        d[6] = make_float2(v1.z, 0.f); d[7] = make_float2(v1.w, 0.f);
    }
    __syncthreads();

    int half = 1;
    #pragma unroll
    for (int st = 0; st < 11; st++) {
        const int step = 1024 / half;
        for (int i = tid; i < 8192; i += 512) {
            int k   = i >> 3;
            int col = i & 7;
            int j   = k & (half - 1);
            int p   = ((k - j) << 1) + j;
            float2 w = tw[j * step];
            float2 u = sa[p * 8 + col];
            float2 v = sa[(p + half) * 8 + col];
            float txr = w.x * v.x - w.y * v.y;
            float txi = w.x * v.y + w.y * v.x;
            sa[p * 8 + col]          = make_float2(u.x + txr, u.y + txi);
            sa[(p + half) * 8 + col] = make_float2(u.x - txr, u.y - txi);
        }
        half <<= 1;
        __syncthreads();
    }

    float* fp = ft + (long)b * S_ * D_;
    for (int i = tid; i < S_ * 8; i += 512) {
        int s   = i >> 3;
        int col = i & 7;
        int dout = (D_ - (c0 + col)) & (D_ - 1);
        fp[(long)s * D_ + dout] = (float)D_ * sa[i].x;
    }
}

// ===========================================================================
// Kernel 2: t = LN(x + ft)*g + b  -> bf16 (hi, lo)
// ===========================================================================
__device__ __forceinline__ float block_sum_256(float val, float* sh) {
    #pragma unroll
    for (int o = 16; o > 0; o >>= 1) val += __shfl_xor_sync(0xFFFFFFFFu, val, o);
    int lane = threadIdx.x & 31, w = threadIdx.x >> 5;
    if (lane == 0) sh[w] = val;
    __syncthreads();
    if (w == 0) {
        float v = (lane < 8) ? sh[lane] : 0.0f;
        #pragma unroll
        for (int o = 4; o > 0; o >>= 1) v += __shfl_xor_sync(0xFFFFFFFFu, v, o);
        if (lane == 0) sh[0] = v;
    }
    __syncthreads();
    float r = sh[0];
    __syncthreads();
    return r;
}

__global__ __launch_bounds__(256) void add_ln_kernel(
    const float* __restrict__ x, const float* __restrict__ ft,
    const float* __restrict__ gamma, const float* __restrict__ beta,
    __nv_bfloat16* __restrict__ thi, __nv_bfloat16* __restrict__ tlo)
{
    __shared__ float sh[8];
    const int row = blockIdx.x;
    const int tid = threadIdx.x;
    const long base = (long)row * D_;

    float v[4];
    float s = 0.0f;
    #pragma unroll
    for (int i = 0; i < 4; i++) {
        int idx = tid + i * 256;
        v[i] = x[base + idx] + ft[base + idx];
        s += v[i];
    }
    float mu = block_sum_256(s, sh) * (1.0f / D_);
    float sq = 0.0f;
    #pragma unroll
    for (int i = 0; i < 4; i++) { float d = v[i] - mu; sq += d * d; }
    float var = block_sum_256(sq, sh) * (1.0f / D_);
    float rs  = rsqrtf(var + 1e-5f);

    #pragma unroll
    for (int i = 0; i < 4; i++) {
        int idx = tid + i * 256;
        float r = (v[i] - mu) * rs * gamma[idx] + beta[idx];
        __nv_bfloat16 hi = __float2bfloat16(r);
        thi[base + idx] = hi;
        tlo[base + idx] = __float2bfloat16(r - __bfloat162float(hi));
    }
}

// ===========================================================================
// Kernel 3/4: bf16 3-term split GEMM via mma.sync (HMMA), fp32 accumulate.
// C[M,N] = A[M,K] @ Wt[N,K]^T.  Tile 128x128x32, 8 warps (2Mx4N, warp 64x32),
// cp.async double buffer.  SMEM rows padded to 80B -> conflict-free ldmatrix.
// fuse 0: bias + exact GELU -> bf16 hi/lo.   fuse 1: bias, *mask -> fp32.
// ===========================================================================
#define BK 32
#define ROWB 80                        // 64B data + 16B pad
#define TILE_B (128 * ROWB)            // 10240
#define STAGE_B (4 * TILE_B)           // Ahi,Alo,Bhi,Blo = 40960
#define GEMM_SMEM (2 * STAGE_B)        // 81920

__global__ __launch_bounds__(256, 1) void gemm_mma_kernel(
    const __nv_bfloat16* __restrict__ Ahi, const __nv_bfloat16* __restrict__ Alo,
    const __nv_bfloat16* __restrict__ Bhi, const __nv_bfloat16* __restrict__ Blo,
    const float* __restrict__ bias, const float* __restrict__ mask,
    __nv_bfloat16* __restrict__ Chi, __nv_bfloat16* __restrict__ Clo,
    float* __restrict__ Cf, int fuse)
{
    extern __shared__ char sm[];
    const uint32_t sb  = smem_u32(sm);
    const int tid  = threadIdx.x;
    const int wid  = tid >> 5;
    const int lane = tid & 31;
    const int bm = blockIdx.y * 128;
    const int bn = blockIdx.x * 128;
    const int warp_m = wid & 1;        // 0..1  -> 64-row slab
    const int warp_n = wid >> 1;       // 0..3  -> 32-col slab

    // ------- stage loader: 512 16B-chunks per tile, 2 per thread per tile ---
    auto load_stage = [&](int stage, int k0) {
        const uint32_t st = sb + stage * STAGE_B;
        #pragma unroll
        for (int t = 0; t < 2; t++) {
            int idx = tid + t * 256;
            int row = idx >> 2;
            int ch  = idx & 3;
            uint32_t so = row * ROWB + ch * 16;
            long ga = (long)(bm + row) * D_ + k0 + ch * 8;
            long gb = (long)(bn + row) * D_ + k0 + ch * 8;
            cp16(st + 0 * TILE_B + so, Ahi + ga);
            cp16(st + 1 * TILE_B + so, Alo + ga);
            cp16(st + 2 * TILE_B + so, Bhi + gb);
            cp16(st + 3 * TILE_B + so, Blo + gb);
        }
    };

    float acc[4][4][4];
    #pragma unroll
    for (int m = 0; m < 4; m++)
        #pragma unroll
        for (int n = 0; n < 4; n++)
            #pragma unroll
            for (int q = 0; q < 4; q++) acc[m][n][q] = 0.0f;

    load_stage(0, 0);
    CP_COMMIT();

    // ldmatrix lane address components
    const int a_lrow = lane & 15;            // row within 16
    const int a_kch  = lane >> 4;            // 16B chunk (k half)
    const int b_lrow = ((lane >> 4) & 1) * 8 + (lane & 7);  // n row within 16
    const int b_kch  = (lane >> 3) & 1;      // 16B chunk (k half)

    const int NIT = D_ / BK;   // 32
    for (int it = 0; it < NIT; it++) {
        const int s = it & 1;
        if (it + 1 < NIT) {
            load_stage(s ^ 1, (it + 1) * BK);
            CP_COMMIT();
            CP_WAIT(1);
        } else {
            CP_WAIT(0);
        }
        __syncthreads();

        const uint32_t tAhi = sb + s * STAGE_B + 0 * TILE_B;
        const uint32_t tAlo = sb + s * STAGE_B + 1 * TILE_B;
        const uint32_t tBhi = sb + s * STAGE_B + 2 * TILE_B;
        const uint32_t tBlo = sb + s * STAGE_B + 3 * TILE_B;

        #pragma unroll
        for (int ks = 0; ks < 2; ks++) {
            const int kb = ks * 32;   // byte offset of 16-elem k chunk
            uint32_t ah[4][4], al[4][4], bh[4][2], bl[4][2];
            #pragma unroll
            for (int m = 0; m < 4; m++) {
                uint32_t off = (uint32_t)((warp_m * 64 + m * 16 + a_lrow) * ROWB
                                          + kb + a_kch * 16);
                ldsm_x4(ah[m], tAhi + off);
                ldsm_x4(al[m], tAlo + off);
            }
            #pragma unroll
            for (int p = 0; p < 2; p++) {
                uint32_t off = (uint32_t)((warp_n * 32 + p * 16 + b_lrow) * ROWB
                                          + kb + b_kch * 16);
                uint32_t r[4];
                ldsm_x4(r, tBhi + off);
                bh[2 * p][0] = r[0]; bh[2 * p][1] = r[1];
                bh[2 * p + 1][0] = r[2]; bh[2 * p + 1][1] = r[3];
                ldsm_x4(r, tBlo + off);
                bl[2 * p][0] = r[0]; bl[2 * p][1] = r[1];
                bl[2 * p + 1][0] = r[2]; bl[2 * p + 1][1] = r[3];
            }
            #pragma unroll
            for (int m = 0; m < 4; m++)
                #pragma unroll
                for (int n = 0; n < 4; n++) {
                    mma_bf16(acc[m][n], ah[m], bh[n]);
                    mma_bf16(acc[m][n], ah[m], bl[n]);
                    mma_bf16(acc[m][n], al[m], bh[n]);
                }
        }
        __syncthreads();
    }

    // ------------------------------ epilogue -------------------------------
    const int g  = lane >> 2;
    const int t2 = (lane & 3) * 2;
    #pragma unroll
    for (int m = 0; m < 4; m++) {
        const int row0 = bm + warp_m * 64 + m * 16 + g;
        #pragma unroll
        for (int half = 0; half < 2; half++) {
            const int row = row0 + half * 8;
            const float mk = (fuse == 1) ? mask[row] : 0.0f;
            #pragma unroll
            for (int n = 0; n < 4; n++) {
                const int col = bn + warp_n * 32 + n * 8 + t2;
                float v0 = acc[m][n][2 * half]     + bias[col];
                float v1 = acc[m][n][2 * half + 1] + bias[col + 1];
                if (fuse == 0) {
                    v0 = 0.5f * v0 * (1.0f + erff(v0 * 0.70710678118654752f));
                    v1 = 0.5f * v1 * (1.0f + erff(v1 * 0.70710678118654752f));
                    __nv_bfloat16 h0 = __float2bfloat16(v0);
                    __nv_bfloat16 h1 = __float2bfloat16(v1);
                    __nv_bfloat16 l0 = __float2bfloat16(v0 - __bfloat162float(h0));
                    __nv_bfloat16 l1 = __float2bfloat16(v1 - __bfloat162float(h1));
                    long off = (long)row * D_ + col;
                    uint32_t hp = ((uint32_t)__bfloat16_as_ushort(h1) << 16)
                                | __bfloat16_as_ushort(h0);
                    uint32_t lp = ((uint32_t)__bfloat16_as_ushort(l1) << 16)
                                | __bfloat16_as_ushort(l0);
                    *(uint32_t*)(Chi + off) = hp;
                    *(uint32_t*)(Clo + off) = lp;
                } else {
                    float2 o = make_float2(v0 * mk, v1 * mk);
                    *(float2*)(Cf + (long)row * D_ + col) = o;
                }
            }
        }
    }
}

// ===========================================================================
// Launch
// ===========================================================================
extern "C" void kernel_launch(void* const* d_in, const int* in_sizes, int n_in,
                              void* d_out, int out_size)
{
    const float* x    = (const float*)d_in[0];
    const float* mask = (const float*)d_in[1];
    const float* ln_g = (const float*)d_in[2];
    const float* ln_b = (const float*)d_in[3];
    const float* w1   = (const float*)d_in[4];
    const float* b1   = (const float*)d_in[5];
    const float* w2   = (const float*)d_in[6];
    const float* b2   = (const float*)d_in[7];
    float* out = (float*)d_out;

    float *ft; float2 *tw;
    __nv_bfloat16 *thi, *tlo, *hhi, *hlo, *w1hi, *w1lo, *w2hi, *w2lo;
    cudaGetSymbolAddress((void**)&ft,   g_ft);
    cudaGetSymbolAddress((void**)&tw,   g_tw);
    cudaGetSymbolAddress((void**)&thi,  g_thi);
    cudaGetSymbolAddress((void**)&tlo,  g_tlo);
    cudaGetSymbolAddress((void**)&hhi,  g_hhi);
    cudaGetSymbolAddress((void**)&hlo,  g_hlo);
    cudaGetSymbolAddress((void**)&w1hi, g_w1hi);
    cudaGetSymbolAddress((void**)&w1lo, g_w1lo);
    cudaGetSymbolAddress((void**)&w2hi, g_w2hi);
    cudaGetSymbolAddress((void**)&w2lo, g_w2lo);

    cudaFuncSetAttribute(fft8_kernel, cudaFuncAttributeMaxDynamicSharedMemorySize, 131072);
    cudaFuncSetAttribute(gemm_mma_kernel, cudaFuncAttributeMaxDynamicSharedMemorySize, GEMM_SMEM);

    twinit_kernel<<<4, 256>>>(tw);
    wsplit_kernel<<<dim3(32, 32), dim3(32, 8)>>>(w1, w1hi, w1lo);
    wsplit_kernel<<<dim3(32, 32), dim3(32, 8)>>>(w2, w2hi, w2lo);
    fft8_kernel<<<dim3(D_ / 8, B_), 512, 131072>>>(x, ft, tw);
    add_ln_kernel<<<ROWS, 256>>>(x, ft, ln_g, ln_b, thi, tlo);
    gemm_mma_kernel<<<dim3(D_ / 128, ROWS / 128), 256, GEMM_SMEM>>>(
        thi, tlo, w1hi, w1lo, b1, nullptr, hhi, hlo, nullptr, 0);
    gemm_mma_kernel<<<dim3(D_ / 128, ROWS / 128), 256, GEMM_SMEM>>>(
        hhi, hlo, w2hi, w2lo, b2, mask, nullptr, nullptr, out, 1);
}

// round 6
// speedup vs baseline: 2.3277x; 1.0798x over previous
#include <cuda_runtime.h>
#include <cuda_bf16.h>
#include <math.h>
#include <stdint.h>

// ===========================================================================
// FNet block on GB300 (compute_103 PTX -> mma.sync HMMA path)
//   ft  = Re(FFT_seq(D * reverse_hidden(x)))   [FFT_D^2 = D * index reversal]
//   t   = LayerNorm(x + ft)*g + b   -> bf16 (hi,lo) split
//   h   = GELU(t @ w1 + b1)         -> bf16x3 mma.sync GEMM, split epilogue
//   out = (h @ w2 + b2) * mask      -> bf16x3 mma.sync GEMM, fp32 epilogue
// FFT: real-packed (2 cols per complex FFT) + fused radix-2 stage pairs.
// ===========================================================================

#define B_ 8
#define S_ 2048
#define D_ 1024
#define ROWS (B_ * S_)
#define ELEMS ((long)ROWS * D_)

__device__ __align__(256) float          g_ft[ELEMS];
__device__ __align__(256) __nv_bfloat16  g_thi[ELEMS];
__device__ __align__(256) __nv_bfloat16  g_tlo[ELEMS];
__device__ __align__(256) __nv_bfloat16  g_hhi[ELEMS];
__device__ __align__(256) __nv_bfloat16  g_hlo[ELEMS];
__device__ __align__(256) __nv_bfloat16  g_w1hi[D_ * D_];
__device__ __align__(256) __nv_bfloat16  g_w1lo[D_ * D_];
__device__ __align__(256) __nv_bfloat16  g_w2hi[D_ * D_];
__device__ __align__(256) __nv_bfloat16  g_w2lo[D_ * D_];
__device__ __align__(256) float2         g_tw[1024];

// ------------------------- helpers ----------------------------------------
__device__ __forceinline__ uint32_t smem_u32(const void* p) {
    uint32_t a;
    asm("{ .reg .u64 t; cvta.to.shared.u64 t, %1; cvt.u32.u64 %0, t; }"
        : "=r"(a) : "l"(p));
    return a;
}
__device__ __forceinline__ void cp16(uint32_t s, const void* g) {
    asm volatile("cp.async.cg.shared.global [%0], [%1], 16;" :: "r"(s), "l"(g));
}
#define CP_COMMIT() asm volatile("cp.async.commit_group;" ::: "memory")
#define CP_WAIT(n)  asm volatile("cp.async.wait_group %0;" :: "n"(n) : "memory")

__device__ __forceinline__ void ldsm_x4(uint32_t* r, uint32_t addr) {
    asm volatile("ldmatrix.sync.aligned.m8n8.x4.shared.b16 {%0,%1,%2,%3}, [%4];"
                 : "=r"(r[0]), "=r"(r[1]), "=r"(r[2]), "=r"(r[3]) : "r"(addr));
}
__device__ __forceinline__ void mma_bf16(float* c, const uint32_t* a, const uint32_t* b) {
    asm volatile("mma.sync.aligned.m16n8k16.row.col.f32.bf16.bf16.f32 "
                 "{%0,%1,%2,%3}, {%4,%5,%6,%7}, {%8,%9}, {%0,%1,%2,%3};"
                 : "+f"(c[0]), "+f"(c[1]), "+f"(c[2]), "+f"(c[3])
                 : "r"(a[0]), "r"(a[1]), "r"(a[2]), "r"(a[3]),
                   "r"(b[0]), "r"(b[1]));
}
__device__ __forceinline__ float2 cmul(float2 a, float2 b) {
    return make_float2(a.x * b.x - a.y * b.y, a.x * b.y + a.y * b.x);
}

// ===========================================================================
// Kernel 0a: twiddle table  tw[t] = exp(-i*pi*t/1024)
// ===========================================================================
__global__ void twinit_kernel(float2* __restrict__ tw) {
    int t = blockIdx.x * 256 + threadIdx.x;
    float s, c;
    sincospif(-(float)t / 1024.0f, &s, &c);
    tw[t] = make_float2(c, s);
}

// ===========================================================================
// Kernel 0b: weight transpose + bf16 hi/lo split.  w[K][N] -> wt_{hi,lo}[N][K]
// ===========================================================================
__global__ __launch_bounds__(256) void wsplit_kernel(
    const float* __restrict__ w, __nv_bfloat16* __restrict__ whi,
    __nv_bfloat16* __restrict__ wlo)
{
    __shared__ float tile[32][33];
    const int bx = blockIdx.x * 32;
    const int by = blockIdx.y * 32;
    const int tx = threadIdx.x, ty = threadIdx.y;
    for (int i = ty; i < 32; i += 8)
        tile[i][tx] = w[(long)(by + i) * D_ + bx + tx];
    __syncthreads();
    for (int i = ty; i < 32; i += 8) {
        int n = bx + i;
        int k = by + tx;
        float v = tile[tx][i];
        __nv_bfloat16 hi = __float2bfloat16(v);
        whi[(long)n * D_ + k] = hi;
        wlo[(long)n * D_ + k] = __float2bfloat16(v - __bfloat162float(hi));
    }
}

// ===========================================================================
// Kernel 1: real-packed FFT along seq. 8 real columns -> 4 complex FFTs.
// Fused stage pairs: rounds h=1,4,16,64,256 (two radix-2 layers each) + h=1024.
// Unpack: ReA[s] = (zr[s]+zr[N-s])/2 ; ReB[s] = (zi[s]+zi[N-s])/2.
// Output col (D - c) & (D-1), scale D.
// ===========================================================================
__global__ __launch_bounds__(512) void fftc_kernel(
    const float* __restrict__ x, float* __restrict__ ft,
    const float2* __restrict__ tw)
{
    extern __shared__ float2 sa[];   // [2048][4] complex = 64 KB
    const int c0  = blockIdx.x * 8;
    const int b   = blockIdx.y;
    const int tid = threadIdx.x;

    const float* xp = x + (long)b * S_ * D_ + c0;
    for (int r = tid; r < S_; r += 512) {
        int br = __brev(r) >> 21;
        float4 v0 = *(const float4*)(xp + (long)r * D_);
        float4 v1 = *(const float4*)(xp + (long)r * D_ + 4);
        float2* d = sa + br * 4;
        d[0] = make_float2(v0.x, v0.y);
        d[1] = make_float2(v0.z, v0.w);
        d[2] = make_float2(v1.x, v1.y);
        d[3] = make_float2(v1.z, v1.w);
    }
    __syncthreads();

    // 5 fused rounds: stages (h, 2h) for h = 1,4,16,64,256
    #pragma unroll
    for (int h = 1; h <= 256; h *= 4) {
        const int step1 = 1024 / h;
        const int step2 = 512 / h;
        #pragma unroll
        for (int t = 0; t < 4; t++) {
            int i = tid + t * 512;
            int q = i & 3;
            int g = i >> 2;                    // group 0..511
            int j = g & (h - 1);
            int i0 = ((g - j) << 2) + j;       // base of 4-element group
            float2 u0 = sa[i0 * 4 + q];
            float2 u1 = sa[(i0 + h) * 4 + q];
            float2 u2 = sa[(i0 + 2 * h) * 4 + q];
            float2 u3 = sa[(i0 + 3 * h) * 4 + q];
            float2 w1 = tw[j * step1];
            float2 wA = tw[j * step2];
            float2 wB = make_float2(wA.y, -wA.x);   // -i * wA
            float2 t1 = cmul(w1, u1);
            float2 a0 = make_float2(u0.x + t1.x, u0.y + t1.y);
            float2 a1 = make_float2(u0.x - t1.x, u0.y - t1.y);
            float2 t3 = cmul(w1, u3);
            float2 a2 = make_float2(u2.x + t3.x, u2.y + t3.y);
            float2 a3 = make_float2(u2.x - t3.x, u2.y - t3.y);
            float2 t2 = cmul(wA, a2);
            float2 tB = cmul(wB, a3);
            sa[i0 * 4 + q]           = make_float2(a0.x + t2.x, a0.y + t2.y);
            sa[(i0 + h) * 4 + q]     = make_float2(a1.x + tB.x, a1.y + tB.y);
            sa[(i0 + 2 * h) * 4 + q] = make_float2(a0.x - t2.x, a0.y - t2.y);
            sa[(i0 + 3 * h) * 4 + q] = make_float2(a1.x - tB.x, a1.y - tB.y);
        }
        __syncthreads();
    }

    // final radix-2 stage, h = 1024
    #pragma unroll
    for (int t = 0; t < 8; t++) {
        int i = tid + t * 512;
        int q = i & 3;
        int p = i >> 2;                        // 0..1023
        float2 w = tw[p];
        float2 u = sa[p * 4 + q];
        float2 v = sa[(p + 1024) * 4 + q];
        float2 tt = cmul(w, v);
        sa[p * 4 + q]            = make_float2(u.x + tt.x, u.y + tt.y);
        sa[(p + 1024) * 4 + q]   = make_float2(u.x - tt.x, u.y - tt.y);
    }
    __syncthreads();

    // unpack real parts + scatter to reversed hidden index, scale by D
    float* fp = ft + (long)b * S_ * D_;
    for (int i = tid; i < S_ * 8; i += 512) {
        int s   = i >> 3;
        int col = i & 7;
        int q   = col >> 1;
        int ns  = (S_ - s) & (S_ - 1);
        float2 zs = sa[s * 4 + q];
        float2 zn = sa[ns * 4 + q];
        float val = (col & 1) ? (zs.y + zn.y) : (zs.x + zn.x);
        val *= 512.0f;                          // D * 0.5
        int dout = (D_ - (c0 + col)) & (D_ - 1);
        fp[(long)s * D_ + dout] = val;
    }
}

// ===========================================================================
// Kernel 2: t = LN(x + ft)*g + b  -> bf16 (hi, lo)
// ===========================================================================
__device__ __forceinline__ float block_sum_256(float val, float* sh) {
    #pragma unroll
    for (int o = 16; o > 0; o >>= 1) val += __shfl_xor_sync(0xFFFFFFFFu, val, o);
    int lane = threadIdx.x & 31, w = threadIdx.x >> 5;
    if (lane == 0) sh[w] = val;
    __syncthreads();
    if (w == 0) {
        float v = (lane < 8) ? sh[lane] : 0.0f;
        #pragma unroll
        for (int o = 4; o > 0; o >>= 1) v += __shfl_xor_sync(0xFFFFFFFFu, v, o);
        if (lane == 0) sh[0] = v;
    }
    __syncthreads();
    float r = sh[0];
    __syncthreads();
    return r;
}

__global__ __launch_bounds__(256) void add_ln_kernel(
    const float* __restrict__ x, const float* __restrict__ ft,
    const float* __restrict__ gamma, const float* __restrict__ beta,
    __nv_bfloat16* __restrict__ thi, __nv_bfloat16* __restrict__ tlo)
{
    __shared__ float sh[8];
    const int row = blockIdx.x;
    const int tid = threadIdx.x;
    const long base = (long)row * D_;

    float v[4];
    float s = 0.0f;
    #pragma unroll
    for (int i = 0; i < 4; i++) {
        int idx = tid + i * 256;
        v[i] = x[base + idx] + ft[base + idx];
        s += v[i];
    }
    float mu = block_sum_256(s, sh) * (1.0f / D_);
    float sq = 0.0f;
    #pragma unroll
    for (int i = 0; i < 4; i++) { float d = v[i] - mu; sq += d * d; }
    float var = block_sum_256(sq, sh) * (1.0f / D_);
    float rs  = rsqrtf(var + 1e-5f);

    #pragma unroll
    for (int i = 0; i < 4; i++) {
        int idx = tid + i * 256;
        float r = (v[i] - mu) * rs * gamma[idx] + beta[idx];
        __nv_bfloat16 hi = __float2bfloat16(r);
        thi[base + idx] = hi;
        tlo[base + idx] = __float2bfloat16(r - __bfloat162float(hi));
    }
}

// ===========================================================================
// Kernel 3/4: bf16x3 split GEMM via mma.sync.  Tile 128M x 256N x 32K,
// 512 threads (16 warps: 4m x 4n, warp tile 32x64), cp.async double buffer.
// SMEM rows padded to 80B. fuse 0: bias+GELU -> bf16 hi/lo. fuse 1: *mask -> f32.
// ===========================================================================
#define BK 32
#define ROWB 80
#define TILE_A_B (128 * ROWB)          // 10240
#define TILE_B_B (256 * ROWB)          // 20480
#define OFF_AHI 0
#define OFF_ALO TILE_A_B
#define OFF_BHI (2 * TILE_A_B)
#define OFF_BLO (2 * TILE_A_B + TILE_B_B)
#define STAGE_B (2 * TILE_A_B + 2 * TILE_B_B)   // 61440
#define GEMM_SMEM (2 * STAGE_B)                 // 122880

__global__ __launch_bounds__(512) void gemm_mma_kernel(
    const __nv_bfloat16* __restrict__ Ahi, const __nv_bfloat16* __restrict__ Alo,
    const __nv_bfloat16* __restrict__ Bhi, const __nv_bfloat16* __restrict__ Blo,
    const float* __restrict__ bias, const float* __restrict__ mask,
    __nv_bfloat16* __restrict__ Chi, __nv_bfloat16* __restrict__ Clo,
    float* __restrict__ Cf, int fuse)
{
    extern __shared__ char sm[];
    const uint32_t sb  = smem_u32(sm);
    const int tid  = threadIdx.x;
    const int wid  = tid >> 5;
    const int lane = tid & 31;
    const int bm = blockIdx.y * 128;
    const int bn = blockIdx.x * 256;
    const int warp_m = wid & 3;        // 32-row slab
    const int warp_n = wid >> 2;       // 64-col slab

    auto load_stage = [&](int stage, int k0) {
        const uint32_t st = sb + stage * STAGE_B;
        {   // A: 512 chunks, 1 per thread (hi + lo)
            int row = tid >> 2, ch = tid & 3;
            uint32_t so = row * ROWB + ch * 16;
            long ga = (long)(bm + row) * D_ + k0 + ch * 8;
            cp16(st + OFF_AHI + so, Ahi + ga);
            cp16(st + OFF_ALO + so, Alo + ga);
        }
        #pragma unroll
        for (int t = 0; t < 2; t++) {   // B: 1024 chunks, 2 per thread
            int idx = tid + t * 512;
            int row = idx >> 2, ch = idx & 3;
            uint32_t so = row * ROWB + ch * 16;
            long gb = (long)(bn + row) * D_ + k0 + ch * 8;
            cp16(st + OFF_BHI + so, Bhi + gb);
            cp16(st + OFF_BLO + so, Blo + gb);
        }
    };

    float acc[2][8][4];
    #pragma unroll
    for (int m = 0; m < 2; m++)
        #pragma unroll
        for (int n = 0; n < 8; n++)
            #pragma unroll
            for (int q = 0; q < 4; q++) acc[m][n][q] = 0.0f;

    load_stage(0, 0);
    CP_COMMIT();

    const int a_lrow = lane & 15;
    const int a_kch  = lane >> 4;
    const int b_lrow = ((lane >> 4) & 1) * 8 + (lane & 7);
    const int b_kch  = (lane >> 3) & 1;

    const int NIT = D_ / BK;   // 32
    for (int it = 0; it < NIT; it++) {
        const int s = it & 1;
        if (it + 1 < NIT) {
            load_stage(s ^ 1, (it + 1) * BK);
            CP_COMMIT();
            CP_WAIT(1);
        } else {
            CP_WAIT(0);
        }
        __syncthreads();

        const uint32_t tAhi = sb + s * STAGE_B + OFF_AHI;
        const uint32_t tAlo = sb + s * STAGE_B + OFF_ALO;
        const uint32_t tBhi = sb + s * STAGE_B + OFF_BHI;
        const uint32_t tBlo = sb + s * STAGE_B + OFF_BLO;

        #pragma unroll
        for (int ks = 0; ks < 2; ks++) {
            const int kb = ks * 32;
            uint32_t ah[2][4], al[2][4];
            #pragma unroll
            for (int m = 0; m < 2; m++) {
                uint32_t off = (uint32_t)((warp_m * 32 + m * 16 + a_lrow) * ROWB
                                          + kb + a_kch * 16);
                ldsm_x4(ah[m], tAhi + off);
                ldsm_x4(al[m], tAlo + off);
            }
            #pragma unroll
            for (int p = 0; p < 4; p++) {
                uint32_t off = (uint32_t)((warp_n * 64 + p * 16 + b_lrow) * ROWB
                                          + kb + b_kch * 16);
                uint32_t rh[4], rl[4];
                ldsm_x4(rh, tBhi + off);
                ldsm_x4(rl, tBlo + off);
                #pragma unroll
                for (int m = 0; m < 2; m++) {
                    mma_bf16(acc[m][2 * p],     ah[m], rh);
                    mma_bf16(acc[m][2 * p],     ah[m], rl);
                    mma_bf16(acc[m][2 * p],     al[m], rh);
                    mma_bf16(acc[m][2 * p + 1], ah[m], rh + 2);
                    mma_bf16(acc[m][2 * p + 1], ah[m], rl + 2);
                    mma_bf16(acc[m][2 * p + 1], al[m], rh + 2);
                }
            }
        }
        __syncthreads();
    }

    // ------------------------------ epilogue -------------------------------
    const int g  = lane >> 2;
    const int t2 = (lane & 3) * 2;
    #pragma unroll
    for (int m = 0; m < 2; m++) {
        const int row0 = bm + warp_m * 32 + m * 16 + g;
        #pragma unroll
        for (int half = 0; half < 2; half++) {
            const int row = row0 + half * 8;
            const float mk = (fuse == 1) ? mask[row] : 0.0f;
            #pragma unroll
            for (int n = 0; n < 8; n++) {
                const int col = bn + warp_n * 64 + n * 8 + t2;
                float v0 = acc[m][n][2 * half]     + bias[col];
                float v1 = acc[m][n][2 * half + 1] + bias[col + 1];
                if (fuse == 0) {
                    v0 = 0.5f * v0 * (1.0f + erff(v0 * 0.70710678118654752f));
                    v1 = 0.5f * v1 * (1.0f + erff(v1 * 0.70710678118654752f));
                    __nv_bfloat16 h0 = __float2bfloat16(v0);
                    __nv_bfloat16 h1 = __float2bfloat16(v1);
                    __nv_bfloat16 l0 = __float2bfloat16(v0 - __bfloat162float(h0));
                    __nv_bfloat16 l1 = __float2bfloat16(v1 - __bfloat162float(h1));
                    long off = (long)row * D_ + col;
                    uint32_t hp = ((uint32_t)__bfloat16_as_ushort(h1) << 16)
                                | __bfloat16_as_ushort(h0);
                    uint32_t lp = ((uint32_t)__bfloat16_as_ushort(l1) << 16)
                                | __bfloat16_as_ushort(l0);
                    *(uint32_t*)(Chi + off) = hp;
                    *(uint32_t*)(Clo + off) = lp;
                } else {
                    float2 o = make_float2(v0 * mk, v1 * mk);
                    *(float2*)(Cf + (long)row * D_ + col) = o;
                }
            }
        }
    }
}

// ===========================================================================
// Launch
// ===========================================================================
extern "C" void kernel_launch(void* const* d_in, const int* in_sizes, int n_in,
                              void* d_out, int out_size)
{
    const float* x    = (const float*)d_in[0];
    const float* mask = (const float*)d_in[1];
    const float* ln_g = (const float*)d_in[2];
    const float* ln_b = (const float*)d_in[3];
    const float* w1   = (const float*)d_in[4];
    const float* b1   = (const float*)d_in[5];
    const float* w2   = (const float*)d_in[6];
    const float* b2   = (const float*)d_in[7];
    float* out = (float*)d_out;

    float *ft; float2 *tw;
    __nv_bfloat16 *thi, *tlo, *hhi, *hlo, *w1hi, *w1lo, *w2hi, *w2lo;
    cudaGetSymbolAddress((void**)&ft,   g_ft);
    cudaGetSymbolAddress((void**)&tw,   g_tw);
    cudaGetSymbolAddress((void**)&thi,  g_thi);
    cudaGetSymbolAddress((void**)&tlo,  g_tlo);
    cudaGetSymbolAddress((void**)&hhi,  g_hhi);
    cudaGetSymbolAddress((void**)&hlo,  g_hlo);
    cudaGetSymbolAddress((void**)&w1hi, g_w1hi);
    cudaGetSymbolAddress((void**)&w1lo, g_w1lo);
    cudaGetSymbolAddress((void**)&w2hi, g_w2hi);
    cudaGetSymbolAddress((void**)&w2lo, g_w2lo);

    cudaFuncSetAttribute(fftc_kernel, cudaFuncAttributeMaxDynamicSharedMemorySize, 65536);
    cudaFuncSetAttribute(gemm_mma_kernel, cudaFuncAttributeMaxDynamicSharedMemorySize, GEMM_SMEM);

    twinit_kernel<<<4, 256>>>(tw);
    wsplit_kernel<<<dim3(32, 32), dim3(32, 8)>>>(w1, w1hi, w1lo);
    wsplit_kernel<<<dim3(32, 32), dim3(32, 8)>>>(w2, w2hi, w2lo);
    fftc_kernel<<<dim3(D_ / 8, B_), 512, 65536>>>(x, ft, tw);
    add_ln_kernel<<<ROWS, 256>>>(x, ft, ln_g, ln_b, thi, tlo);
    gemm_mma_kernel<<<dim3(D_ / 256, ROWS / 128), 512, GEMM_SMEM>>>(
        thi, tlo, w1hi, w1lo, b1, nullptr, hhi, hlo, nullptr, 0);
    gemm_mma_kernel<<<dim3(D_ / 256, ROWS / 128), 512, GEMM_SMEM>>>(
        hhi, hlo, w2hi, w2lo, b2, mask, nullptr, nullptr, out, 1);
}

// round 7
// speedup vs baseline: 3.0379x; 1.3051x over previous
#include <cuda_runtime.h>
#include <cuda_bf16.h>
#include <cuda_fp16.h>
#include <math.h>
#include <stdint.h>

// ===========================================================================
// FNet block on GB300 (compute_103 PTX -> mma.sync HMMA path)
//   ft  = Re(FFT_seq(D * reverse_hidden(x)))   [FFT_D^2 = D * index reversal]
//   t   = LayerNorm(x + ft)*g + b   -> fp16 (hi,lo) split
//   h   = GELU(t @ w1 + b1)         -> 2-term fp16 mma GEMM, split epilogue
//   out = (h @ w2 + b2) * mask      -> 2-term fp16 mma GEMM, fp32 epilogue
// 2-term trick: A = Ahi + Alo (fp16 pair, ~22 bits); W rounded once to fp16.
// Only error is fp16(W) rounding: rel ~3e-4 per GEMM.
// ===========================================================================

#define B_ 8
#define S_ 2048
#define D_ 1024
#define ROWS (B_ * S_)
#define ELEMS ((long)ROWS * D_)

__device__ __align__(256) float   g_ft[ELEMS];
__device__ __align__(256) __half  g_thi[ELEMS];
__device__ __align__(256) __half  g_tlo[ELEMS];
__device__ __align__(256) __half  g_hhi[ELEMS];
__device__ __align__(256) __half  g_hlo[ELEMS];
__device__ __align__(256) __half  g_w1h[D_ * D_];
__device__ __align__(256) __half  g_w2h[D_ * D_];
__device__ __align__(256) float2  g_tw[1024];

// ------------------------- helpers ----------------------------------------
__device__ __forceinline__ uint32_t smem_u32(const void* p) {
    uint32_t a;
    asm("{ .reg .u64 t; cvta.to.shared.u64 t, %1; cvt.u32.u64 %0, t; }"
        : "=r"(a) : "l"(p));
    return a;
}
__device__ __forceinline__ void cp16(uint32_t s, const void* g) {
    asm volatile("cp.async.cg.shared.global [%0], [%1], 16;" :: "r"(s), "l"(g));
}
#define CP_COMMIT() asm volatile("cp.async.commit_group;" ::: "memory")
#define CP_WAIT(n)  asm volatile("cp.async.wait_group %0;" :: "n"(n) : "memory")

__device__ __forceinline__ void ldsm_x4(uint32_t* r, uint32_t addr) {
    asm volatile("ldmatrix.sync.aligned.m8n8.x4.shared.b16 {%0,%1,%2,%3}, [%4];"
                 : "=r"(r[0]), "=r"(r[1]), "=r"(r[2]), "=r"(r[3]) : "r"(addr));
}
__device__ __forceinline__ void mma_f16(float* c, const uint32_t* a, const uint32_t* b) {
    asm volatile("mma.sync.aligned.m16n8k16.row.col.f32.f16.f16.f32 "
                 "{%0,%1,%2,%3}, {%4,%5,%6,%7}, {%8,%9}, {%0,%1,%2,%3};"
                 : "+f"(c[0]), "+f"(c[1]), "+f"(c[2]), "+f"(c[3])
                 : "r"(a[0]), "r"(a[1]), "r"(a[2]), "r"(a[3]),
                   "r"(b[0]), "r"(b[1]));
}
__device__ __forceinline__ float2 cmul(float2 a, float2 b) {
    return make_float2(a.x * b.x - a.y * b.y, a.x * b.y + a.y * b.x);
}

// ===========================================================================
// Kernel 0a: twiddle table  tw[t] = exp(-i*pi*t/1024)
// ===========================================================================
__global__ void twinit_kernel(float2* __restrict__ tw) {
    int t = blockIdx.x * 256 + threadIdx.x;
    float s, c;
    sincospif(-(float)t / 1024.0f, &s, &c);
    tw[t] = make_float2(c, s);
}

// ===========================================================================
// Kernel 0b: weight transpose + fp16 convert.  w[K][N] -> wt[N][K] fp16
// ===========================================================================
__global__ __launch_bounds__(256) void wsplit_kernel(
    const float* __restrict__ w, __half* __restrict__ wh)
{
    __shared__ float tile[32][33];
    const int bx = blockIdx.x * 32;
    const int by = blockIdx.y * 32;
    const int tx = threadIdx.x, ty = threadIdx.y;
    for (int i = ty; i < 32; i += 8)
        tile[i][tx] = w[(long)(by + i) * D_ + bx + tx];
    __syncthreads();
    for (int i = ty; i < 32; i += 8) {
        int n = bx + i;
        int k = by + tx;
        wh[(long)n * D_ + k] = __float2half(tile[tx][i]);
    }
}

// ===========================================================================
// Kernel 1: real-packed FFT along seq (8 real cols -> 4 complex FFTs),
// fused radix-4 rounds + final radix-2; unpack Re, scatter reversed, scale D.
// ===========================================================================
__global__ __launch_bounds__(512) void fftc_kernel(
    const float* __restrict__ x, float* __restrict__ ft,
    const float2* __restrict__ tw)
{
    extern __shared__ float2 sa[];   // [2048][4] complex = 64 KB
    const int c0  = blockIdx.x * 8;
    const int b   = blockIdx.y;
    const int tid = threadIdx.x;

    const float* xp = x + (long)b * S_ * D_ + c0;
    for (int r = tid; r < S_; r += 512) {
        int br = __brev(r) >> 21;
        float4 v0 = *(const float4*)(xp + (long)r * D_);
        float4 v1 = *(const float4*)(xp + (long)r * D_ + 4);
        float2* d = sa + br * 4;
        d[0] = make_float2(v0.x, v0.y);
        d[1] = make_float2(v0.z, v0.w);
        d[2] = make_float2(v1.x, v1.y);
        d[3] = make_float2(v1.z, v1.w);
    }
    __syncthreads();

    #pragma unroll
    for (int h = 1; h <= 256; h *= 4) {
        const int step1 = 1024 / h;
        const int step2 = 512 / h;
        #pragma unroll
        for (int t = 0; t < 4; t++) {
            int i = tid + t * 512;
            int q = i & 3;
            int g = i >> 2;
            int j = g & (h - 1);
            int i0 = ((g - j) << 2) + j;
            float2 u0 = sa[i0 * 4 + q];
            float2 u1 = sa[(i0 + h) * 4 + q];
            float2 u2 = sa[(i0 + 2 * h) * 4 + q];
            float2 u3 = sa[(i0 + 3 * h) * 4 + q];
            float2 w1 = tw[j * step1];
            float2 wA = tw[j * step2];
            float2 wB = make_float2(wA.y, -wA.x);
            float2 t1 = cmul(w1, u1);
            float2 a0 = make_float2(u0.x + t1.x, u0.y + t1.y);
            float2 a1 = make_float2(u0.x - t1.x, u0.y - t1.y);
            float2 t3 = cmul(w1, u3);
            float2 a2 = make_float2(u2.x + t3.x, u2.y + t3.y);
            float2 a3 = make_float2(u2.x - t3.x, u2.y - t3.y);
            float2 t2 = cmul(wA, a2);
            float2 tB = cmul(wB, a3);
            sa[i0 * 4 + q]           = make_float2(a0.x + t2.x, a0.y + t2.y);
            sa[(i0 + h) * 4 + q]     = make_float2(a1.x + tB.x, a1.y + tB.y);
            sa[(i0 + 2 * h) * 4 + q] = make_float2(a0.x - t2.x, a0.y - t2.y);
            sa[(i0 + 3 * h) * 4 + q] = make_float2(a1.x - tB.x, a1.y - tB.y);
        }
        __syncthreads();
    }

    #pragma unroll
    for (int t = 0; t < 8; t++) {
        int i = tid + t * 512;
        int q = i & 3;
        int p = i >> 2;
        float2 w = tw[p];
        float2 u = sa[p * 4 + q];
        float2 v = sa[(p + 1024) * 4 + q];
        float2 tt = cmul(w, v);
        sa[p * 4 + q]          = make_float2(u.x + tt.x, u.y + tt.y);
        sa[(p + 1024) * 4 + q] = make_float2(u.x - tt.x, u.y - tt.y);
    }
    __syncthreads();

    float* fp = ft + (long)b * S_ * D_;
    for (int i = tid; i < S_ * 8; i += 512) {
        int s   = i >> 3;
        int col = i & 7;
        int q   = col >> 1;
        int ns  = (S_ - s) & (S_ - 1);
        float2 zs = sa[s * 4 + q];
        float2 zn = sa[ns * 4 + q];
        float val = (col & 1) ? (zs.y + zn.y) : (zs.x + zn.x);
        val *= 512.0f;                          // D * 0.5
        int dout = (D_ - (c0 + col)) & (D_ - 1);
        fp[(long)s * D_ + dout] = val;
    }
}

// ===========================================================================
// Kernel 2: t = LN(x + ft)*g + b  -> fp16 (hi, lo)
// ===========================================================================
__device__ __forceinline__ float block_sum_256(float val, float* sh) {
    #pragma unroll
    for (int o = 16; o > 0; o >>= 1) val += __shfl_xor_sync(0xFFFFFFFFu, val, o);
    int lane = threadIdx.x & 31, w = threadIdx.x >> 5;
    if (lane == 0) sh[w] = val;
    __syncthreads();
    if (w == 0) {
        float v = (lane < 8) ? sh[lane] : 0.0f;
        #pragma unroll
        for (int o = 4; o > 0; o >>= 1) v += __shfl_xor_sync(0xFFFFFFFFu, v, o);
        if (lane == 0) sh[0] = v;
    }
    __syncthreads();
    float r = sh[0];
    __syncthreads();
    return r;
}

__global__ __launch_bounds__(256) void add_ln_kernel(
    const float* __restrict__ x, const float* __restrict__ ft,
    const float* __restrict__ gamma, const float* __restrict__ beta,
    __half* __restrict__ thi, __half* __restrict__ tlo)
{
    __shared__ float sh[8];
    const int row = blockIdx.x;
    const int tid = threadIdx.x;
    const long base = (long)row * D_;

    float v[4];
    float s = 0.0f;
    #pragma unroll
    for (int i = 0; i < 4; i++) {
        int idx = tid + i * 256;
        v[i] = x[base + idx] + ft[base + idx];
        s += v[i];
    }
    float mu = block_sum_256(s, sh) * (1.0f / D_);
    float sq = 0.0f;
    #pragma unroll
    for (int i = 0; i < 4; i++) { float d = v[i] - mu; sq += d * d; }
    float var = block_sum_256(sq, sh) * (1.0f / D_);
    float rs  = rsqrtf(var + 1e-5f);

    #pragma unroll
    for (int i = 0; i < 4; i++) {
        int idx = tid + i * 256;
        float r = (v[i] - mu) * rs * gamma[idx] + beta[idx];
        __half hi = __float2half(r);
        thi[base + idx] = hi;
        tlo[base + idx] = __float2half(r - __half2float(hi));
    }
}

// ===========================================================================
// Kernel 3/4: 2-term fp16 GEMM via mma.sync. Tile 128M x 256N x 32K,
// 512 threads (16 warps: 4m x 4n, warp tile 32x64), cp.async double buffer.
// fuse 0: bias+GELU -> fp16 hi/lo.   fuse 1: bias, *mask -> fp32.
// ===========================================================================
#define BK 32
#define ROWB 80
#define TILE_A_B (128 * ROWB)          // 10240
#define TILE_B_B (256 * ROWB)          // 20480
#define OFF_AHI 0
#define OFF_ALO TILE_A_B
#define OFF_BW  (2 * TILE_A_B)
#define STAGE_B (2 * TILE_A_B + TILE_B_B)   // 40960
#define GEMM_SMEM (2 * STAGE_B)             // 81920

__global__ __launch_bounds__(512) void gemm_mma_kernel(
    const __half* __restrict__ Ahi, const __half* __restrict__ Alo,
    const __half* __restrict__ Bw,
    const float* __restrict__ bias, const float* __restrict__ mask,
    __half* __restrict__ Chi, __half* __restrict__ Clo,
    float* __restrict__ Cf, int fuse)
{
    extern __shared__ char sm[];
    const uint32_t sb  = smem_u32(sm);
    const int tid  = threadIdx.x;
    const int wid  = tid >> 5;
    const int lane = tid & 31;
    const int bm = blockIdx.y * 128;
    const int bn = blockIdx.x * 256;
    const int warp_m = wid & 3;
    const int warp_n = wid >> 2;

    auto load_stage = [&](int stage, int k0) {
        const uint32_t st = sb + stage * STAGE_B;
        {   // A: 512 chunks hi + 512 lo, 1 each per thread
            int row = tid >> 2, ch = tid & 3;
            uint32_t so = row * ROWB + ch * 16;
            long ga = (long)(bm + row) * D_ + k0 + ch * 8;
            cp16(st + OFF_AHI + so, Ahi + ga);
            cp16(st + OFF_ALO + so, Alo + ga);
        }
        #pragma unroll
        for (int t = 0; t < 2; t++) {   // W: 1024 chunks, 2 per thread
            int idx = tid + t * 512;
            int row = idx >> 2, ch = idx & 3;
            uint32_t so = row * ROWB + ch * 16;
            long gb = (long)(bn + row) * D_ + k0 + ch * 8;
            cp16(st + OFF_BW + so, Bw + gb);
        }
    };

    float acc[2][8][4];
    #pragma unroll
    for (int m = 0; m < 2; m++)
        #pragma unroll
        for (int n = 0; n < 8; n++)
            #pragma unroll
            for (int q = 0; q < 4; q++) acc[m][n][q] = 0.0f;

    load_stage(0, 0);
    CP_COMMIT();

    const int a_lrow = lane & 15;
    const int a_kch  = lane >> 4;
    const int b_lrow = ((lane >> 4) & 1) * 8 + (lane & 7);
    const int b_kch  = (lane >> 3) & 1;

    const int NIT = D_ / BK;   // 32
    for (int it = 0; it < NIT; it++) {
        const int s = it & 1;
        if (it + 1 < NIT) {
            load_stage(s ^ 1, (it + 1) * BK);
            CP_COMMIT();
            CP_WAIT(1);
        } else {
            CP_WAIT(0);
        }
        __syncthreads();

        const uint32_t tAhi = sb + s * STAGE_B + OFF_AHI;
        const uint32_t tAlo = sb + s * STAGE_B + OFF_ALO;
        const uint32_t tBw  = sb + s * STAGE_B + OFF_BW;

        #pragma unroll
        for (int ks = 0; ks < 2; ks++) {
            const int kb = ks * 32;
            uint32_t ah[2][4], al[2][4];
            #pragma unroll
            for (int m = 0; m < 2; m++) {
                uint32_t off = (uint32_t)((warp_m * 32 + m * 16 + a_lrow) * ROWB
                                          + kb + a_kch * 16);
                ldsm_x4(ah[m], tAhi + off);
                ldsm_x4(al[m], tAlo + off);
            }
            #pragma unroll
            for (int p = 0; p < 4; p++) {
                uint32_t off = (uint32_t)((warp_n * 64 + p * 16 + b_lrow) * ROWB
                                          + kb + b_kch * 16);
                uint32_t rh[4];
                ldsm_x4(rh, tBw + off);
                #pragma unroll
                for (int m = 0; m < 2; m++) {
                    mma_f16(acc[m][2 * p],     ah[m], rh);
                    mma_f16(acc[m][2 * p],     al[m], rh);
                    mma_f16(acc[m][2 * p + 1], ah[m], rh + 2);
                    mma_f16(acc[m][2 * p + 1], al[m], rh + 2);
                }
            }
        }
        __syncthreads();
    }

    // ------------------------------ epilogue -------------------------------
    const int g  = lane >> 2;
    const int t2 = (lane & 3) * 2;
    #pragma unroll
    for (int m = 0; m < 2; m++) {
        const int row0 = bm + warp_m * 32 + m * 16 + g;
        #pragma unroll
        for (int half = 0; half < 2; half++) {
            const int row = row0 + half * 8;
            const float mk = (fuse == 1) ? mask[row] : 0.0f;
            #pragma unroll
            for (int n = 0; n < 8; n++) {
                const int col = bn + warp_n * 64 + n * 8 + t2;
                float v0 = acc[m][n][2 * half]     + bias[col];
                float v1 = acc[m][n][2 * half + 1] + bias[col + 1];
                if (fuse == 0) {
                    v0 = 0.5f * v0 * (1.0f + erff(v0 * 0.70710678118654752f));
                    v1 = 0.5f * v1 * (1.0f + erff(v1 * 0.70710678118654752f));
                    __half h0 = __float2half(v0);
                    __half h1 = __float2half(v1);
                    __half l0 = __float2half(v0 - __half2float(h0));
                    __half l1 = __float2half(v1 - __half2float(h1));
                    long off = (long)row * D_ + col;
                    uint32_t hp = ((uint32_t)__half_as_ushort(h1) << 16)
                                | __half_as_ushort(h0);
                    uint32_t lp = ((uint32_t)__half_as_ushort(l1) << 16)
                                | __half_as_ushort(l0);
                    *(uint32_t*)(Chi + off) = hp;
                    *(uint32_t*)(Clo + off) = lp;
                } else {
                    float2 o = make_float2(v0 * mk, v1 * mk);
                    *(float2*)(Cf + (long)row * D_ + col) = o;
                }
            }
        }
    }
}

// ===========================================================================
// Launch
// ===========================================================================
extern "C" void kernel_launch(void* const* d_in, const int* in_sizes, int n_in,
                              void* d_out, int out_size)
{
    const float* x    = (const float*)d_in[0];
    const float* mask = (const float*)d_in[1];
    const float* ln_g = (const float*)d_in[2];
    const float* ln_b = (const float*)d_in[3];
    const float* w1   = (const float*)d_in[4];
    const float* b1   = (const float*)d_in[5];
    const float* w2   = (const float*)d_in[6];
    const float* b2   = (const float*)d_in[7];
    float* out = (float*)d_out;

    float *ft; float2 *tw;
    __half *thi, *tlo, *hhi, *hlo, *w1h, *w2h;
    cudaGetSymbolAddress((void**)&ft,  g_ft);
    cudaGetSymbolAddress((void**)&tw,  g_tw);
    cudaGetSymbolAddress((void**)&thi, g_thi);
    cudaGetSymbolAddress((void**)&tlo, g_tlo);
    cudaGetSymbolAddress((void**)&hhi, g_hhi);
    cudaGetSymbolAddress((void**)&hlo, g_hlo);
    cudaGetSymbolAddress((void**)&w1h, g_w1h);
    cudaGetSymbolAddress((void**)&w2h, g_w2h);

    cudaFuncSetAttribute(fftc_kernel, cudaFuncAttributeMaxDynamicSharedMemorySize, 65536);
    cudaFuncSetAttribute(gemm_mma_kernel, cudaFuncAttributeMaxDynamicSharedMemorySize, GEMM_SMEM);

    twinit_kernel<<<4, 256>>>(tw);
    wsplit_kernel<<<dim3(32, 32), dim3(32, 8)>>>(w1, w1h);
    wsplit_kernel<<<dim3(32, 32), dim3(32, 8)>>>(w2, w2h);
    fftc_kernel<<<dim3(D_ / 8, B_), 512, 65536>>>(x, ft, tw);
    add_ln_kernel<<<ROWS, 256>>>(x, ft, ln_g, ln_b, thi, tlo);
    gemm_mma_kernel<<<dim3(D_ / 256, ROWS / 128), 512, GEMM_SMEM>>>(
        thi, tlo, w1h, b1, nullptr, hhi, hlo, nullptr, 0);
    gemm_mma_kernel<<<dim3(D_ / 256, ROWS / 128), 512, GEMM_SMEM>>>(
        hhi, hlo, w2h, b2, mask, nullptr, nullptr, out, 1);
}

// round 8
// speedup vs baseline: 4.3041x; 1.4168x over previous
#include <cuda_runtime.h>
#include <cuda_bf16.h>
#include <cuda_fp16.h>
#include <math.h>
#include <stdint.h>

// ===========================================================================
// FNet block on GB300 (compute_103 PTX -> mma.sync HMMA path)
//   ft  = Re(FFT_seq(D * reverse_hidden(x)))   [FFT_D^2 = D * index reversal]
//   t   = LayerNorm(x + ft)*g + b   -> fp16
//   h   = GELU(t @ w1 + b1)         -> 1-term fp16 mma GEMM -> fp16
//   out = (h @ w2 + b2) * mask      -> 1-term fp16 mma GEMM -> fp32
// Error budget (norm-RMS): 2 weight + 2 activation fp16 roundings ~ 3.3e-4.
// ===========================================================================

#define B_ 8
#define S_ 2048
#define D_ 1024
#define ROWS (B_ * S_)
#define ELEMS ((long)ROWS * D_)

__device__ __align__(256) float   g_ft[ELEMS];
__device__ __align__(256) __half  g_t[ELEMS];
__device__ __align__(256) __half  g_h[ELEMS];
__device__ __align__(256) __half  g_w1h[D_ * D_];
__device__ __align__(256) __half  g_w2h[D_ * D_];
__device__ __align__(256) float2  g_tw[1024];

// ------------------------- helpers ----------------------------------------
__device__ __forceinline__ uint32_t smem_u32(const void* p) {
    uint32_t a;
    asm("{ .reg .u64 t; cvta.to.shared.u64 t, %1; cvt.u32.u64 %0, t; }"
        : "=r"(a) : "l"(p));
    return a;
}
__device__ __forceinline__ void cp16(uint32_t s, const void* g) {
    asm volatile("cp.async.cg.shared.global [%0], [%1], 16;" :: "r"(s), "l"(g));
}
#define CP_COMMIT() asm volatile("cp.async.commit_group;" ::: "memory")
#define CP_WAIT(n)  asm volatile("cp.async.wait_group %0;" :: "n"(n) : "memory")

__device__ __forceinline__ void ldsm_x4(uint32_t* r, uint32_t addr) {
    asm volatile("ldmatrix.sync.aligned.m8n8.x4.shared.b16 {%0,%1,%2,%3}, [%4];"
                 : "=r"(r[0]), "=r"(r[1]), "=r"(r[2]), "=r"(r[3]) : "r"(addr));
}
__device__ __forceinline__ void mma_f16(float* c, const uint32_t* a, const uint32_t* b) {
    asm volatile("mma.sync.aligned.m16n8k16.row.col.f32.f16.f16.f32 "
                 "{%0,%1,%2,%3}, {%4,%5,%6,%7}, {%8,%9}, {%0,%1,%2,%3};"
                 : "+f"(c[0]), "+f"(c[1]), "+f"(c[2]), "+f"(c[3])
                 : "r"(a[0]), "r"(a[1]), "r"(a[2]), "r"(a[3]),
                   "r"(b[0]), "r"(b[1]));
}
__device__ __forceinline__ float2 cmul(float2 a, float2 b) {
    return make_float2(a.x * b.x - a.y * b.y, a.x * b.y + a.y * b.x);
}

// ===========================================================================
// Kernel 0a: twiddle table  tw[t] = exp(-i*pi*t/1024)
// ===========================================================================
__global__ void twinit_kernel(float2* __restrict__ tw) {
    int t = blockIdx.x * 256 + threadIdx.x;
    float s, c;
    sincospif(-(float)t / 1024.0f, &s, &c);
    tw[t] = make_float2(c, s);
}

// ===========================================================================
// Kernel 0b: weight transpose + fp16 convert.  w[K][N] -> wt[N][K] fp16
// ===========================================================================
__global__ __launch_bounds__(256) void wsplit_kernel(
    const float* __restrict__ w, __half* __restrict__ wh)
{
    __shared__ float tile[32][33];
    const int bx = blockIdx.x * 32;
    const int by = blockIdx.y * 32;
    const int tx = threadIdx.x, ty = threadIdx.y;
    for (int i = ty; i < 32; i += 8)
        tile[i][tx] = w[(long)(by + i) * D_ + bx + tx];
    __syncthreads();
    for (int i = ty; i < 32; i += 8) {
        int n = bx + i;
        int k = by + tx;
        wh[(long)n * D_ + k] = __float2half(tile[tx][i]);
    }
}

// ===========================================================================
// Kernel 1: real-packed FFT along seq (8 real cols -> 4 complex FFTs),
// fused radix-4 rounds + final radix-2; unpack Re, scatter reversed, scale D.
// ===========================================================================
__global__ __launch_bounds__(512) void fftc_kernel(
    const float* __restrict__ x, float* __restrict__ ft,
    const float2* __restrict__ tw)
{
    extern __shared__ float2 sa[];   // [2048][4] complex = 64 KB
    const int c0  = blockIdx.x * 8;
    const int b   = blockIdx.y;
    const int tid = threadIdx.x;

    const float* xp = x + (long)b * S_ * D_ + c0;
    for (int r = tid; r < S_; r += 512) {
        int br = __brev(r) >> 21;
        float4 v0 = *(const float4*)(xp + (long)r * D_);
        float4 v1 = *(const float4*)(xp + (long)r * D_ + 4);
        float2* d = sa + br * 4;
        d[0] = make_float2(v0.x, v0.y);
        d[1] = make_float2(v0.z, v0.w);
        d[2] = make_float2(v1.x, v1.y);
        d[3] = make_float2(v1.z, v1.w);
    }
    __syncthreads();

    #pragma unroll
    for (int h = 1; h <= 256; h *= 4) {
        const int step1 = 1024 / h;
        const int step2 = 512 / h;
        #pragma unroll
        for (int t = 0; t < 4; t++) {
            int i = tid + t * 512;
            int q = i & 3;
            int g = i >> 2;
            int j = g & (h - 1);
            int i0 = ((g - j) << 2) + j;
            float2 u0 = sa[i0 * 4 + q];
            float2 u1 = sa[(i0 + h) * 4 + q];
            float2 u2 = sa[(i0 + 2 * h) * 4 + q];
            float2 u3 = sa[(i0 + 3 * h) * 4 + q];
            float2 w1 = tw[j * step1];
            float2 wA = tw[j * step2];
            float2 wB = make_float2(wA.y, -wA.x);
            float2 t1 = cmul(w1, u1);
            float2 a0 = make_float2(u0.x + t1.x, u0.y + t1.y);
            float2 a1 = make_float2(u0.x - t1.x, u0.y - t1.y);
            float2 t3 = cmul(w1, u3);
            float2 a2 = make_float2(u2.x + t3.x, u2.y + t3.y);
            float2 a3 = make_float2(u2.x - t3.x, u2.y - t3.y);
            float2 t2 = cmul(wA, a2);
            float2 tB = cmul(wB, a3);
            sa[i0 * 4 + q]           = make_float2(a0.x + t2.x, a0.y + t2.y);
            sa[(i0 + h) * 4 + q]     = make_float2(a1.x + tB.x, a1.y + tB.y);
            sa[(i0 + 2 * h) * 4 + q] = make_float2(a0.x - t2.x, a0.y - t2.y);
            sa[(i0 + 3 * h) * 4 + q] = make_float2(a1.x - tB.x, a1.y - tB.y);
        }
        __syncthreads();
    }

    #pragma unroll
    for (int t = 0; t < 8; t++) {
        int i = tid + t * 512;
        int q = i & 3;
        int p = i >> 2;
        float2 w = tw[p];
        float2 u = sa[p * 4 + q];
        float2 v = sa[(p + 1024) * 4 + q];
        float2 tt = cmul(w, v);
        sa[p * 4 + q]          = make_float2(u.x + tt.x, u.y + tt.y);
        sa[(p + 1024) * 4 + q] = make_float2(u.x - tt.x, u.y - tt.y);
    }
    __syncthreads();

    float* fp = ft + (long)b * S_ * D_;
    for (int i = tid; i < S_ * 8; i += 512) {
        int s   = i >> 3;
        int col = i & 7;
        int q   = col >> 1;
        int ns  = (S_ - s) & (S_ - 1);
        float2 zs = sa[s * 4 + q];
        float2 zn = sa[ns * 4 + q];
        float val = (col & 1) ? (zs.y + zn.y) : (zs.x + zn.x);
        val *= 512.0f;                          // D * 0.5
        int dout = (D_ - (c0 + col)) & (D_ - 1);
        fp[(long)s * D_ + dout] = val;
    }
}

// ===========================================================================
// Kernel 2: t = LN(x + ft)*g + b  -> fp16
// ===========================================================================
__device__ __forceinline__ float block_sum_256(float val, float* sh) {
    #pragma unroll
    for (int o = 16; o > 0; o >>= 1) val += __shfl_xor_sync(0xFFFFFFFFu, val, o);
    int lane = threadIdx.x & 31, w = threadIdx.x >> 5;
    if (lane == 0) sh[w] = val;
    __syncthreads();
    if (w == 0) {
        float v = (lane < 8) ? sh[lane] : 0.0f;
        #pragma unroll
        for (int o = 4; o > 0; o >>= 1) v += __shfl_xor_sync(0xFFFFFFFFu, v, o);
        if (lane == 0) sh[0] = v;
    }
    __syncthreads();
    float r = sh[0];
    __syncthreads();
    return r;
}

__global__ __launch_bounds__(256) void add_ln_kernel(
    const float* __restrict__ x, const float* __restrict__ ft,
    const float* __restrict__ gamma, const float* __restrict__ beta,
    __half* __restrict__ t_out)
{
    __shared__ float sh[8];
    const int row = blockIdx.x;
    const int tid = threadIdx.x;
    const long base = (long)row * D_;

    float v[4];
    float s = 0.0f;
    #pragma unroll
    for (int i = 0; i < 4; i++) {
        int idx = tid + i * 256;
        v[i] = x[base + idx] + ft[base + idx];
        s += v[i];
    }
    float mu = block_sum_256(s, sh) * (1.0f / D_);
    float sq = 0.0f;
    #pragma unroll
    for (int i = 0; i < 4; i++) { float d = v[i] - mu; sq += d * d; }
    float var = block_sum_256(sq, sh) * (1.0f / D_);
    float rs  = rsqrtf(var + 1e-5f);

    #pragma unroll
    for (int i = 0; i < 4; i++) {
        int idx = tid + i * 256;
        float r = (v[i] - mu) * rs * gamma[idx] + beta[idx];
        t_out[base + idx] = __float2half(r);
    }
}

// ===========================================================================
// Kernel 3/4: 1-term fp16 GEMM via mma.sync. Tile 128M x 256N x 32K,
// 512 threads (16 warps: 4m x 4n, warp tile 32x64), cp.async double buffer.
// fuse 0: bias+GELU -> fp16.   fuse 1: bias, *mask -> fp32.
// ===========================================================================
#define BK 32
#define ROWB 80
#define TILE_A_B (128 * ROWB)          // 10240
#define TILE_B_B (256 * ROWB)          // 20480
#define OFF_A 0
#define OFF_BW TILE_A_B
#define STAGE_B (TILE_A_B + TILE_B_B)       // 30720
#define GEMM_SMEM (2 * STAGE_B)             // 61440

__global__ __launch_bounds__(512) void gemm_mma_kernel(
    const __half* __restrict__ A, const __half* __restrict__ Bw,
    const float* __restrict__ bias, const float* __restrict__ mask,
    __half* __restrict__ Ch, float* __restrict__ Cf, int fuse)
{
    extern __shared__ char sm[];
    const uint32_t sb  = smem_u32(sm);
    const int tid  = threadIdx.x;
    const int wid  = tid >> 5;
    const int lane = tid & 31;
    const int bm = blockIdx.y * 128;
    const int bn = blockIdx.x * 256;
    const int warp_m = wid & 3;
    const int warp_n = wid >> 2;

    auto load_stage = [&](int stage, int k0) {
        const uint32_t st = sb + stage * STAGE_B;
        {   // A: 512 chunks, 1 per thread
            int row = tid >> 2, ch = tid & 3;
            uint32_t so = row * ROWB + ch * 16;
            long ga = (long)(bm + row) * D_ + k0 + ch * 8;
            cp16(st + OFF_A + so, A + ga);
        }
        #pragma unroll
        for (int t = 0; t < 2; t++) {   // W: 1024 chunks, 2 per thread
            int idx = tid + t * 512;
            int row = idx >> 2, ch = idx & 3;
            uint32_t so = row * ROWB + ch * 16;
            long gb = (long)(bn + row) * D_ + k0 + ch * 8;
            cp16(st + OFF_BW + so, Bw + gb);
        }
    };

    float acc[2][8][4];
    #pragma unroll
    for (int m = 0; m < 2; m++)
        #pragma unroll
        for (int n = 0; n < 8; n++)
            #pragma unroll
            for (int q = 0; q < 4; q++) acc[m][n][q] = 0.0f;

    load_stage(0, 0);
    CP_COMMIT();

    const int a_lrow = lane & 15;
    const int a_kch  = lane >> 4;
    const int b_lrow = ((lane >> 4) & 1) * 8 + (lane & 7);
    const int b_kch  = (lane >> 3) & 1;

    const int NIT = D_ / BK;   // 32
    for (int it = 0; it < NIT; it++) {
        const int s = it & 1;
        if (it + 1 < NIT) {
            load_stage(s ^ 1, (it + 1) * BK);
            CP_COMMIT();
            CP_WAIT(1);
        } else {
            CP_WAIT(0);
        }
        __syncthreads();

        const uint32_t tA  = sb + s * STAGE_B + OFF_A;
        const uint32_t tBw = sb + s * STAGE_B + OFF_BW;

        #pragma unroll
        for (int ks = 0; ks < 2; ks++) {
            const int kb = ks * 32;
            uint32_t ah[2][4];
            #pragma unroll
            for (int m = 0; m < 2; m++) {
                uint32_t off = (uint32_t)((warp_m * 32 + m * 16 + a_lrow) * ROWB
                                          + kb + a_kch * 16);
                ldsm_x4(ah[m], tA + off);
            }
            #pragma unroll
            for (int p = 0; p < 4; p++) {
                uint32_t off = (uint32_t)((warp_n * 64 + p * 16 + b_lrow) * ROWB
                                          + kb + b_kch * 16);
                uint32_t rh[4];
                ldsm_x4(rh, tBw + off);
                #pragma unroll
                for (int m = 0; m < 2; m++) {
                    mma_f16(acc[m][2 * p],     ah[m], rh);
                    mma_f16(acc[m][2 * p + 1], ah[m], rh + 2);
                }
            }
        }
        __syncthreads();
    }

    // ------------------------------ epilogue -------------------------------
    const int g  = lane >> 2;
    const int t2 = (lane & 3) * 2;
    #pragma unroll
    for (int m = 0; m < 2; m++) {
        const int row0 = bm + warp_m * 32 + m * 16 + g;
        #pragma unroll
        for (int half = 0; half < 2; half++) {
            const int row = row0 + half * 8;
            const float mk = (fuse == 1) ? mask[row] : 0.0f;
            #pragma unroll
            for (int n = 0; n < 8; n++) {
                const int col = bn + warp_n * 64 + n * 8 + t2;
                float v0 = acc[m][n][2 * half]     + bias[col];
                float v1 = acc[m][n][2 * half + 1] + bias[col + 1];
                if (fuse == 0) {
                    v0 = 0.5f * v0 * (1.0f + erff(v0 * 0.70710678118654752f));
                    v1 = 0.5f * v1 * (1.0f + erff(v1 * 0.70710678118654752f));
                    __half h0 = __float2half(v0);
                    __half h1 = __float2half(v1);
                    uint32_t hp = ((uint32_t)__half_as_ushort(h1) << 16)
                                | __half_as_ushort(h0);
                    *(uint32_t*)(Ch + (long)row * D_ + col) = hp;
                } else {
                    float2 o = make_float2(v0 * mk, v1 * mk);
                    *(float2*)(Cf + (long)row * D_ + col) = o;
                }
            }
        }
    }
}

// ===========================================================================
// Launch
// ===========================================================================
extern "C" void kernel_launch(void* const* d_in, const int* in_sizes, int n_in,
                              void* d_out, int out_size)
{
    const float* x    = (const float*)d_in[0];
    const float* mask = (const float*)d_in[1];
    const float* ln_g = (const float*)d_in[2];
    const float* ln_b = (const float*)d_in[3];
    const float* w1   = (const float*)d_in[4];
    const float* b1   = (const float*)d_in[5];
    const float* w2   = (const float*)d_in[6];
    const float* b2   = (const float*)d_in[7];
    float* out = (float*)d_out;

    float *ft; float2 *tw;
    __half *t, *h, *w1h, *w2h;
    cudaGetSymbolAddress((void**)&ft,  g_ft);
    cudaGetSymbolAddress((void**)&tw,  g_tw);
    cudaGetSymbolAddress((void**)&t,   g_t);
    cudaGetSymbolAddress((void**)&h,   g_h);
    cudaGetSymbolAddress((void**)&w1h, g_w1h);
    cudaGetSymbolAddress((void**)&w2h, g_w2h);

    cudaFuncSetAttribute(fftc_kernel, cudaFuncAttributeMaxDynamicSharedMemorySize, 65536);
    cudaFuncSetAttribute(gemm_mma_kernel, cudaFuncAttributeMaxDynamicSharedMemorySize, GEMM_SMEM);

    twinit_kernel<<<4, 256>>>(tw);
    wsplit_kernel<<<dim3(32, 32), dim3(32, 8)>>>(w1, w1h);
    wsplit_kernel<<<dim3(32, 32), dim3(32, 8)>>>(w2, w2h);
    fftc_kernel<<<dim3(D_ / 8, B_), 512, 65536>>>(x, ft, tw);
    add_ln_kernel<<<ROWS, 256>>>(x, ft, ln_g, ln_b, t);
    gemm_mma_kernel<<<dim3(D_ / 256, ROWS / 128), 512, GEMM_SMEM>>>(
        t, w1h, b1, nullptr, h, nullptr, 0);
    gemm_mma_kernel<<<dim3(D_ / 256, ROWS / 128), 512, GEMM_SMEM>>>(
        h, w2h, b2, mask, nullptr, out, 1);
}